// round 1
// baseline (speedup 1.0000x reference)
#include <cuda_runtime.h>

// Inverted window cross-attention, fp32 with packed f32x2 FMAs.
// One CTA per (window, head): 1024 x 6 = 6144 CTAs, 128 threads each.
// score[n][m] = 2 - scale*(q2[n].k1[m] + k2[n].q1[m]); softmax rows; out = attn @ (v1+v2).

#define NT 64          // tokens per window (8x8)
#define HD 32          // head dim
#define PAD 34         // smem row pitch (floats), keeps 8B alignment, conflict-free with interleaved-m
#define SROW 65        // score row pitch (floats)

typedef unsigned long long ull;

constexpr int Bc = 4, Hc = 128, Wc = 128, Cc = 192;
constexpr int Lc = Hc * Wc;
constexpr long long BLC = (long long)Bc * Lc * Cc;

__device__ __forceinline__ void fma2(ull& d, ull a, ull b) {
    asm("fma.rn.f32x2 %0, %1, %2, %0;" : "+l"(d) : "l"(a), "l"(b));
}
__device__ __forceinline__ ull pk2(float lo, float hi) {
    ull r; asm("mov.b64 %0, {%1, %2};" : "=l"(r) : "f"(lo), "f"(hi)); return r;
}
__device__ __forceinline__ float2 up2(ull v) {
    float2 f; asm("mov.b64 {%0, %1}, %2;" : "=f"(f.x), "=f"(f.y) : "l"(v)); return f;
}
__device__ __forceinline__ void st4(float* p, float4 v) {
    *(float2*)p       = make_float2(v.x, v.y);
    *(float2*)(p + 2) = make_float2(v.z, v.w);
}

__global__ __launch_bounds__(128, 3)
void inv_attn_kernel(const float* __restrict__ qkv1,
                     const float* __restrict__ qkv2,
                     float* __restrict__ out)
{
    extern __shared__ float sm[];
    float* sQ2 = sm;                 // [NT][PAD]
    float* sK2 = sQ2 + NT * PAD;
    float* sK1 = sK2 + NT * PAD;
    float* sQ1 = sK1 + NT * PAD;
    float* sV  = sQ1 + NT * PAD;     // v1 + v2
    float* sS  = sV  + NT * PAD;     // [NT][SROW] scores
    float* sInv = sS + NT * SROW;    // [NT] 1/rowsum

    const int tid  = threadIdx.x;
    const int win  = blockIdx.x;     // 0..1023
    const int head = blockIdx.y;     // 0..5
    const int b  = win >> 8;
    const int hb = (win >> 4) & 15;
    const int wb = win & 15;
    const int row0  = (hb * 8) * Wc + wb * 8;   // top-left token row in L
    const int cbase = head * HD;

    // ---------------- load (6 gmem tiles -> 5 smem tiles) ----------------
    {
        const int t  = tid >> 1;            // token 0..63
        const int d0 = (tid & 1) * 16;      // half of head_dim
        const int hs = t >> 3, ws = t & 7;
        const long long grow = ((long long)b * Lc + row0 + hs * Wc + ws) * Cc + cbase;
        const float* q1g = qkv1 + grow;
        const float* k1g = qkv1 + BLC + grow;
        const float* v1g = qkv1 + 2 * BLC + grow;
        const float* v2g = qkv1 + 3 * BLC + grow;
        const float* q2g = qkv2 + grow;
        const float* k2g = qkv2 + BLC + grow;
        const int sb = t * PAD;
#pragma unroll
        for (int k = 0; k < 4; k++) {
            const int d = d0 + k * 4;
            st4(sQ2 + sb + d, *(const float4*)(q2g + d));
            st4(sK2 + sb + d, *(const float4*)(k2g + d));
            st4(sK1 + sb + d, *(const float4*)(k1g + d));
            st4(sQ1 + sb + d, *(const float4*)(q1g + d));
            float4 y = *(const float4*)(v1g + d);
            float4 z = *(const float4*)(v2g + d);
            y.x += z.x; y.y += z.y; y.z += z.z; y.w += z.w;
            st4(sV + sb + d, y);
        }
    }
    __syncthreads();

    // ---------------- scores: 8x4 register tile per thread ----------------
    {
        const int ty = tid >> 4;   // 0..7  -> n rows: ty + 8*i
        const int tx = tid & 15;   // 0..15 -> m cols: tx + 16*j
        ull acc[8][4] = {};
#pragma unroll 4
        for (int d = 0; d < HD; d += 2) {
            ull a1[8], a2[8], b1[4], b2[4];
#pragma unroll
            for (int i = 0; i < 8; i++) {
                const int n = (ty + 8 * i) * PAD + d;
                a1[i] = *(const ull*)(sQ2 + n);
                a2[i] = *(const ull*)(sK2 + n);
            }
#pragma unroll
            for (int j = 0; j < 4; j++) {
                const int m = (tx + 16 * j) * PAD + d;
                b1[j] = *(const ull*)(sK1 + m);
                b2[j] = *(const ull*)(sQ1 + m);
            }
#pragma unroll
            for (int i = 0; i < 8; i++)
#pragma unroll
                for (int j = 0; j < 4; j++) {
                    fma2(acc[i][j], a1[i], b1[j]);
                    fma2(acc[i][j], a2[i], b2[j]);
                }
        }
        const float scale = 0.17677669529663687f;  // 32^-0.5
#pragma unroll
        for (int i = 0; i < 8; i++)
#pragma unroll
            for (int j = 0; j < 4; j++) {
                float2 f = up2(acc[i][j]);
                sS[(ty + 8 * i) * SROW + tx + 16 * j] = 2.0f - scale * (f.x + f.y);
            }
    }
    __syncthreads();

    // ---------------- softmax (fold 1/sum into PV epilogue) ----------------
    {
        const int row = tid >> 1;
        const int seg = tid & 1;
        float* rp = sS + row * SROW + seg * 32;
        float mx = -1e30f;
#pragma unroll
        for (int k = 0; k < 32; k++) mx = fmaxf(mx, rp[k]);
        mx = fmaxf(mx, __shfl_xor_sync(0xffffffffu, mx, 1));
        float sum = 0.f;
#pragma unroll
        for (int k = 0; k < 32; k++) {
            float e = __expf(rp[k] - mx);
            rp[k] = e;
            sum += e;
        }
        sum += __shfl_xor_sync(0xffffffffu, sum, 1);
        if (!seg) sInv[row] = 1.0f / sum;
    }
    __syncthreads();

    // ---------------- PV: 4 rows x 4 cols per thread ----------------
    {
        const int ty2 = tid >> 3;       // 0..15 -> rows ty2 + 16*i
        const int tx2 = tid & 7;        // 0..7  -> dd = 4*tx2
        const int dd = tx2 * 4;
        ull o[4][2] = {};
#pragma unroll 8
        for (int m = 0; m < NT; m++) {
            const ull v0 = *(const ull*)(sV + m * PAD + dd);
            const ull v1 = *(const ull*)(sV + m * PAD + dd + 2);
#pragma unroll
            for (int i = 0; i < 4; i++) {
                const float a = sS[(ty2 + 16 * i) * SROW + m];
                const ull ad = pk2(a, a);
                fma2(o[i][0], ad, v0);
                fma2(o[i][1], ad, v1);
            }
        }
#pragma unroll
        for (int i = 0; i < 4; i++) {
            const int n = ty2 + 16 * i;
            const float inv = sInv[n];
            const float2 p = up2(o[i][0]);
            const float2 q = up2(o[i][1]);
            const long long g =
                ((long long)b * Lc + row0 + (n >> 3) * Wc + (n & 7)) * Cc + cbase + dd;
            *(float4*)(out + g) = make_float4(p.x * inv, p.y * inv, q.x * inv, q.y * inv);
        }
    }
}

extern "C" void kernel_launch(void* const* d_in, const int* in_sizes, int n_in,
                              void* d_out, int out_size)
{
    const float* qkv1 = (const float*)d_in[0];
    const float* qkv2 = (const float*)d_in[1];
    float* out = (float*)d_out;

    const int smem_bytes = (5 * NT * PAD + NT * SROW + NT) * (int)sizeof(float);  // 60416
    cudaFuncSetAttribute(inv_attn_kernel,
                         cudaFuncAttributeMaxDynamicSharedMemorySize, smem_bytes);
    inv_attn_kernel<<<dim3(1024, 6, 1), 128, smem_bytes>>>(qkv1, qkv2, out);
}

// round 2
// speedup vs baseline: 1.0283x; 1.0283x over previous
#include <cuda_runtime.h>

// Inverted window cross-attention, fp32 with packed f32x2 FMAs.
// One CTA per (window, head): 1024 x 6 = 6144 CTAs, 128 threads.
// score[n][m] = 2 - scale*(q2[n].k1[m] + k2[n].q1[m]); softmax rows; out = attn @ (v1+v2).

#define NT 64          // tokens per window (8x8)
#define HD 32          // head dim
#define PADQ 34        // Q/K smem row pitch (floats)
#define PADV 36        // V pitch (16B-aligned rows for LDS.128)
#define SROW 66        // score row pitch (8B-aligned, conflict-min for LDS.64)

typedef unsigned long long ull;

constexpr int Bc = 4, Hc = 128, Wc = 128, Cc = 192;
constexpr int Lc = Hc * Wc;
constexpr long long BLC = (long long)Bc * Lc * Cc;

__device__ __forceinline__ void fma2(ull& d, ull a, ull b) {
    asm("fma.rn.f32x2 %0, %1, %2, %0;" : "+l"(d) : "l"(a), "l"(b));
}
__device__ __forceinline__ ull pk2(float lo, float hi) {
    ull r; asm("mov.b64 %0, {%1, %2};" : "=l"(r) : "f"(lo), "f"(hi)); return r;
}
__device__ __forceinline__ float2 up2(ull v) {
    float2 f; asm("mov.b64 {%0, %1}, %2;" : "=f"(f.x), "=f"(f.y) : "l"(v)); return f;
}
__device__ __forceinline__ void st4_64(float* p, float4 v) {
    *(float2*)p       = make_float2(v.x, v.y);
    *(float2*)(p + 2) = make_float2(v.z, v.w);
}

__global__ __launch_bounds__(128, 4)
void inv_attn_kernel(const float* __restrict__ qkv1,
                     const float* __restrict__ qkv2,
                     float* __restrict__ out)
{
    extern __shared__ float sm[];
    // Layout: [Q2 | K2 | K1 | Q1 | V | inv]; scores overlay Q2+K2 after they die.
    float* sQ2 = sm;
    float* sK2 = sm + NT * PADQ;
    float* sK1 = sm + 2 * NT * PADQ;
    float* sQ1 = sm + 3 * NT * PADQ;
    float* sV  = sm + 4 * NT * PADQ;          // pitch PADV
    float* sInv = sV + NT * PADV;
    float* sS  = sm;                          // [NT][SROW] = 4224 fl <= 4352 fl (Q2+K2)

    const int tid  = threadIdx.x;
    const int win  = blockIdx.x;
    const int head = blockIdx.y;
    const int b  = win >> 8;
    const int hb = (win >> 4) & 15;
    const int wb = win & 15;
    const int row0  = (hb * 8) * Wc + wb * 8;
    const int cbase = head * HD;

    // ---------------- load: 6 gmem tiles -> 5 smem tiles ----------------
    {
        const int t  = tid >> 1;            // token 0..63
        const int d0 = (tid & 1) * 16;
        const int hs = t >> 3, ws = t & 7;
        const long long grow = ((long long)b * Lc + row0 + hs * Wc + ws) * Cc + cbase;
        const float* q1g = qkv1 + grow;
        const float* k1g = qkv1 + BLC + grow;
        const float* v1g = qkv1 + 2 * BLC + grow;
        const float* v2g = qkv1 + 3 * BLC + grow;
        const float* q2g = qkv2 + grow;
        const float* k2g = qkv2 + BLC + grow;
#pragma unroll
        for (int k = 0; k < 2; k++) {
            const int d = d0 + k * 8;
#pragma unroll
            for (int dd = 0; dd < 8; dd += 4) {
                st4_64(sQ2 + t * PADQ + d + dd, *(const float4*)(q2g + d + dd));
                st4_64(sK2 + t * PADQ + d + dd, *(const float4*)(k2g + d + dd));
                st4_64(sK1 + t * PADQ + d + dd, *(const float4*)(k1g + d + dd));
                st4_64(sQ1 + t * PADQ + d + dd, *(const float4*)(q1g + d + dd));
                float4 y = *(const float4*)(v1g + d + dd);
                float4 z = *(const float4*)(v2g + d + dd);
                y.x += z.x; y.y += z.y; y.z += z.z; y.w += z.w;
                *(float4*)(sV + t * PADV + d + dd) = y;     // 16B-aligned
            }
        }
    }
    __syncthreads();

    // ---------------- scores: 8x4 register tile per thread ----------------
    {
        const int ty = tid >> 4;   // 0..7  -> rows ty + 8*i
        const int tx = tid & 15;   // 0..15 -> cols tx + 16*j
        ull acc[8][4] = {};
#pragma unroll 4
        for (int d = 0; d < HD; d += 2) {
            ull a[8], bb[4];
#pragma unroll
            for (int i = 0; i < 8; i++) a[i] = *(const ull*)(sQ2 + (ty + 8 * i) * PADQ + d);
#pragma unroll
            for (int j = 0; j < 4; j++) bb[j] = *(const ull*)(sK1 + (tx + 16 * j) * PADQ + d);
#pragma unroll
            for (int i = 0; i < 8; i++)
#pragma unroll
                for (int j = 0; j < 4; j++) fma2(acc[i][j], a[i], bb[j]);
#pragma unroll
            for (int i = 0; i < 8; i++) a[i] = *(const ull*)(sK2 + (ty + 8 * i) * PADQ + d);
#pragma unroll
            for (int j = 0; j < 4; j++) bb[j] = *(const ull*)(sQ1 + (tx + 16 * j) * PADQ + d);
#pragma unroll
            for (int i = 0; i < 8; i++)
#pragma unroll
                for (int j = 0; j < 4; j++) fma2(acc[i][j], a[i], bb[j]);
        }
        __syncthreads();   // Q2/K2 fully consumed by ALL threads; safe to overwrite with scores
        const float scale = 0.17677669529663687f;  // 32^-0.5
#pragma unroll
        for (int i = 0; i < 8; i++)
#pragma unroll
            for (int j = 0; j < 4; j++) {
                float2 f = up2(acc[i][j]);
                sS[(ty + 8 * i) * SROW + tx + 16 * j] = 2.0f - scale * (f.x + f.y);
            }
    }
    __syncthreads();

    // ---------------- softmax (vectorized LDS.64; 1/sum folded into PV epilogue) --------
    {
        const int row = tid >> 1;
        const int seg = tid & 1;
        float* rp = sS + row * SROW + seg * 32;
        ull u[16];
#pragma unroll
        for (int k = 0; k < 16; k++) u[k] = *(const ull*)(rp + 2 * k);
        float mx = -1e30f;
#pragma unroll
        for (int k = 0; k < 16; k++) {
            float2 f = up2(u[k]);
            mx = fmaxf(mx, fmaxf(f.x, f.y));
        }
        mx = fmaxf(mx, __shfl_xor_sync(0xffffffffu, mx, 1));
        float sum = 0.f;
#pragma unroll
        for (int k = 0; k < 16; k++) {
            float2 f = up2(u[k]);
            float e0 = __expf(f.x - mx);
            float e1 = __expf(f.y - mx);
            sum += e0 + e1;
            *(ull*)(rp + 2 * k) = pk2(e0, e1);
        }
        sum += __shfl_xor_sync(0xffffffffu, sum, 1);
        if (!seg) sInv[row] = 1.0f / sum;
    }
    __syncthreads();

    // ---------------- PV: 4 rows x 4 cols per thread, m in pairs ----------------
    {
        const int ty2 = tid >> 3;       // 0..15 -> rows ty2 + 16*i
        const int tx2 = tid & 7;        // 0..7  -> dd = 4*tx2
        const int dd = tx2 * 4;
        ull o[4][2] = {};
#pragma unroll 4
        for (int m = 0; m < NT; m += 2) {
            ull av[4];
#pragma unroll
            for (int i = 0; i < 4; i++)
                av[i] = *(const ull*)(sS + (ty2 + 16 * i) * SROW + m);
            const ulonglong2 v0 = *(const ulonglong2*)(sV + m * PADV + dd);
            const ulonglong2 v1 = *(const ulonglong2*)(sV + (m + 1) * PADV + dd);
#pragma unroll
            for (int i = 0; i < 4; i++) {
                float2 aa = up2(av[i]);
                const ull s0 = pk2(aa.x, aa.x);
                const ull s1 = pk2(aa.y, aa.y);
                fma2(o[i][0], s0, v0.x);
                fma2(o[i][1], s0, v0.y);
                fma2(o[i][0], s1, v1.x);
                fma2(o[i][1], s1, v1.y);
            }
        }
#pragma unroll
        for (int i = 0; i < 4; i++) {
            const int n = ty2 + 16 * i;
            const float inv = sInv[n];
            const float2 p = up2(o[i][0]);
            const float2 q = up2(o[i][1]);
            const long long g =
                ((long long)b * Lc + row0 + (n >> 3) * Wc + (n & 7)) * Cc + cbase + dd;
            *(float4*)(out + g) = make_float4(p.x * inv, p.y * inv, q.x * inv, q.y * inv);
        }
    }
}

extern "C" void kernel_launch(void* const* d_in, const int* in_sizes, int n_in,
                              void* d_out, int out_size)
{
    const float* qkv1 = (const float*)d_in[0];
    const float* qkv2 = (const float*)d_in[1];
    float* out = (float*)d_out;

    const int smem_bytes = (4 * NT * PADQ + NT * PADV + NT) * (int)sizeof(float);  // 44288
    cudaFuncSetAttribute(inv_attn_kernel,
                         cudaFuncAttributeMaxDynamicSharedMemorySize, smem_bytes);
    inv_attn_kernel<<<dim3(1024, 6, 1), 128, smem_bytes>>>(qkv1, qkv2, out);
}